// round 17
// baseline (speedup 1.0000x reference)
#include <cuda_runtime.h>
#include <cuda_bf16.h>
#include <math.h>
#include <stdint.h>

#define NB 4
#define NC 256
#define NPIX 16384
#define NHEADS 8
#define CH 32
#define GK 6

// ------------------------- scratch ------------------------------------------
__device__ float  g_S[NB * NC];
__device__ float  g_part[8 * NB * 2 * NC * NC];
__device__ float  g_C0[NB * NC * NC];
__device__ float  g_Cf[NB * NC * NC];
__device__ float  g_P[3 * NB * NC * NC];
__device__ float2 g_At[NB * NHEADS * CH * CH];
__device__ float2 g_Dtab[128 * 256];
__device__ unsigned short g_xh[(size_t)NB * NC * NPIX];
__device__ unsigned short g_xl[(size_t)NB * NC * NPIX];
__device__ unsigned short g_xfh[(size_t)NB * NC * NPIX];
__device__ unsigned short g_xfl[(size_t)NB * NC * NPIX];
__device__ unsigned short g_vsh[(size_t)NB * NC * NPIX];
__device__ unsigned short g_vsl[(size_t)NB * NC * NPIX];
__device__ unsigned short g_wh[2 * NC * NC];
__device__ unsigned short g_wl[2 * NC * NC];
__device__ uint32_t g_y2[(size_t)NB * NPIX * NC];
__device__ unsigned short g_DreH[128 * 128 * 128];
__device__ unsigned short g_DreL[128 * 128 * 128];
__device__ unsigned short g_DimH[128 * 128 * 128];
__device__ unsigned short g_DimL[128 * 128 * 128];

// ------------------------- mma.sync helpers ----------------------------------
__device__ __forceinline__ uint32_t smem_u32(const void* p) {
    uint32_t a;
    asm("{ .reg .u64 t; cvta.to.shared.u64 t, %1; cvt.u32.u64 %0, t; }" : "=r"(a) : "l"(p));
    return a;
}
__device__ __forceinline__ void MMA(float* d, const uint32_t* a, const uint32_t* b) {
    asm volatile("mma.sync.aligned.m16n8k16.row.col.f32.bf16.bf16.f32 "
        "{%0,%1,%2,%3}, {%4,%5,%6,%7}, {%8,%9}, {%0,%1,%2,%3};"
        : "+f"(d[0]), "+f"(d[1]), "+f"(d[2]), "+f"(d[3])
        : "r"(a[0]), "r"(a[1]), "r"(a[2]), "r"(a[3]), "r"(b[0]), "r"(b[1]));
}
__device__ __forceinline__ void ldm_x4(uint32_t* r, uint32_t a) {
    asm volatile("ldmatrix.sync.aligned.m8n8.x4.shared.b16 {%0,%1,%2,%3}, [%4];"
        : "=r"(r[0]), "=r"(r[1]), "=r"(r[2]), "=r"(r[3]) : "r"(a));
}
__device__ __forceinline__ void ldm_x2(uint32_t* r, uint32_t a) {
    asm volatile("ldmatrix.sync.aligned.m8n8.x2.shared.b16 {%0,%1}, [%2];"
        : "=r"(r[0]), "=r"(r[1]) : "r"(a));
}
__device__ __forceinline__ void ldm_x2t(uint32_t* r, uint32_t a) {
    asm volatile("ldmatrix.sync.aligned.m8n8.x2.trans.shared.b16 {%0,%1}, [%2];"
        : "=r"(r[0]), "=r"(r[1]) : "r"(a));
}
__device__ __forceinline__ void split_pack(float4 v, uint2& hi, uint2& lo) {
    __nv_bfloat16 h0 = __float2bfloat16_rn(v.x), h1 = __float2bfloat16_rn(v.y);
    __nv_bfloat16 h2 = __float2bfloat16_rn(v.z), h3 = __float2bfloat16_rn(v.w);
    __nv_bfloat16 l0 = __float2bfloat16_rn(v.x - __bfloat162float(h0));
    __nv_bfloat16 l1 = __float2bfloat16_rn(v.y - __bfloat162float(h1));
    __nv_bfloat16 l2 = __float2bfloat16_rn(v.z - __bfloat162float(h2));
    __nv_bfloat16 l3 = __float2bfloat16_rn(v.w - __bfloat162float(h3));
    hi.x = (uint32_t)__bfloat16_as_ushort(h0) | ((uint32_t)__bfloat16_as_ushort(h1) << 16);
    hi.y = (uint32_t)__bfloat16_as_ushort(h2) | ((uint32_t)__bfloat16_as_ushort(h3) << 16);
    lo.x = (uint32_t)__bfloat16_as_ushort(l0) | ((uint32_t)__bfloat16_as_ushort(l1) << 16);
    lo.y = (uint32_t)__bfloat16_as_ushort(l2) | ((uint32_t)__bfloat16_as_ushort(l3) << 16);
}
__device__ __forceinline__ uint32_t pack_hl(float y) {
    __nv_bfloat16 h = __float2bfloat16_rn(y);
    __nv_bfloat16 l = __float2bfloat16_rn(y - __bfloat162float(h));
    return (uint32_t)__bfloat16_as_ushort(h) | ((uint32_t)__bfloat16_as_ushort(l) << 16);
}
__device__ __forceinline__ void pack2(float a, float b, uint32_t& hi, uint32_t& lo) {
    __nv_bfloat16 ha = __float2bfloat16_rn(a), hb = __float2bfloat16_rn(b);
    __nv_bfloat16 la = __float2bfloat16_rn(a - __bfloat162float(ha));
    __nv_bfloat16 lb = __float2bfloat16_rn(b - __bfloat162float(hb));
    hi = (uint32_t)__bfloat16_as_ushort(ha) | ((uint32_t)__bfloat16_as_ushort(hb) << 16);
    lo = (uint32_t)__bfloat16_as_ushort(la) | ((uint32_t)__bfloat16_as_ushort(lb) << 16);
}

// ------------------------- fused sum + x split (+ warp-shuffle flip) ---------
__global__ __launch_bounds__(256) void k_sumsplit(const float* __restrict__ x) {
    int bc = blockIdx.x;
    const float4* p = (const float4*)(x + (size_t)bc * NPIX);
    uint2* Xh = (uint2*)g_xh + (size_t)bc * 4096;
    uint2* Xl = (uint2*)g_xl + (size_t)bc * 4096;
    uint2* Fh = (uint2*)g_xfh + (size_t)bc * 4096;
    uint2* Fl = (uint2*)g_xfl + (size_t)bc * 4096;
    int warp = threadIdx.x >> 5, lane = threadIdx.x & 31;
    int srcR = 31 - lane, src0 = (32 - lane) & 31;
    float s = 0.f;
    for (int rr = 0; rr < 16; ++rr) {
        int row = warp * 16 + rr;
        int idx = row * 32 + lane;
        float4 v = p[idx];
        uint2 hi, lo;
        split_pack(v, hi, lo);
        Xh[idx] = hi; Xl[idx] = lo;
        s += (v.x + v.y) + (v.z + v.w);
        uint32_t rhx = __shfl_sync(0xFFFFFFFFu, hi.x, srcR);
        uint32_t rhy = __shfl_sync(0xFFFFFFFFu, hi.y, srcR);
        uint32_t rlx = __shfl_sync(0xFFFFFFFFu, lo.x, srcR);
        uint32_t rly = __shfl_sync(0xFFFFFFFFu, lo.y, srcR);
        uint32_t e0h = __shfl_sync(0xFFFFFFFFu, hi.x, src0);
        uint32_t e0l = __shfl_sync(0xFFFFFFFFu, lo.x, src0);
        uint2 oh, ol;
        oh.x = (e0h & 0xFFFFu) | (rhy & 0xFFFF0000u);
        oh.y = (rhy & 0xFFFFu) | (rhx & 0xFFFF0000u);
        ol.x = (e0l & 0xFFFFu) | (rly & 0xFFFF0000u);
        ol.y = (rly & 0xFFFFu) | (rlx & 0xFFFF0000u);
        int frow = (128 - row) & 127;
        Fh[frow * 32 + lane] = oh;
        Fl[frow * 32 + lane] = ol;
    }
    __shared__ float sm[256];
    sm[threadIdx.x] = s; __syncthreads();
    for (int w = 128; w > 0; w >>= 1) {
        if (threadIdx.x < w) sm[threadIdx.x] += sm[threadIdx.x + w];
        __syncthreads();
    }
    if (threadIdx.x == 0) g_S[bc] = sm[0];
}
__global__ __launch_bounds__(256) void k_wsplit(const float* __restrict__ w3,
                                                const float* __restrict__ wo) {
    int gid = blockIdx.x * 256 + threadIdx.x;
    int per = NC * NC / 4;
    int m = gid / per, e = gid % per;
    const float* src = (m == 0 ? w3 : wo);
    float4 v = ((const float4*)src)[e];
    uint2 hi, lo;
    split_pack(v, hi, lo);
    ((uint2*)g_wh)[gid] = hi;
    ((uint2*)g_wl)[gid] = lo;
}

// ------------------------- Gram via mma.sync (512 thr, 1-wave grid) ----------
#define GSA 40
#define GTILE (128 * GSA)
#define GBUF (4 * GTILE)
#define GSMEM (2 * GBUF * 2)
__global__ __launch_bounds__(512, 1) void k_gram_mma() {
    extern __shared__ __align__(16) __nv_bfloat16 smg[];
    int tid = threadIdx.x, wid = tid >> 5, lane = tid & 31;
    int tile = blockIdx.x;
    int i0 = (tile == 2) ? 128 : 0;
    int j0 = (tile == 0) ? 0 : 128;
    int b = blockIdx.y, ks = blockIdx.z >> 1, mode = blockIdx.z & 1;
    const unsigned short* Xh = g_xh + (size_t)b * NC * NPIX;
    const unsigned short* Xl = g_xl + (size_t)b * NC * NPIX;
    const unsigned short* Bh_g = (mode == 0 ? g_xh : g_xfh) + (size_t)b * NC * NPIX;
    const unsigned short* Bl_g = (mode == 0 ? g_xl : g_xfl) + (size_t)b * NC * NPIX;
    int wm = wid >> 2, wn = wid & 3;                   // 4 x 4 warp grid, 32x32 tiles
    float acc[2][4][4] = {};
    uint2 pAh[2], pAl[2], pBh[2], pBl[2];

    auto LD = [&](int ch) {
        int Kc = ch * 32;
#pragma unroll
        for (int q = 0; q < 2; ++q) {
            int f = tid + q * 512, r = f >> 3, c = (f & 7) * 4;
            size_t off = (size_t)(i0 + r) * NPIX + Kc + c;
            pAh[q] = *(const uint2*)(Xh + off);
            pAl[q] = *(const uint2*)(Xl + off);
        }
#pragma unroll
        for (int q = 0; q < 2; ++q) {
            int f = tid + q * 512, r = f >> 3, c = (f & 7) * 4;
            size_t off = (size_t)(j0 + r) * NPIX + Kc + c;
            pBh[q] = *(const uint2*)(Bh_g + off);
            pBl[q] = *(const uint2*)(Bl_g + off);
        }
    };
    auto ST = [&](int buf) {
        __nv_bfloat16* Ah = smg + buf * GBUF;
        __nv_bfloat16* Al = Ah + GTILE;
        __nv_bfloat16* Bh = Ah + 2 * GTILE;
        __nv_bfloat16* Bl = Ah + 3 * GTILE;
#pragma unroll
        for (int q = 0; q < 2; ++q) {
            int f = tid + q * 512, r = f >> 3, c = (f & 7) * 4;
            *(uint2*)(Ah + r * GSA + c) = pAh[q];
            *(uint2*)(Al + r * GSA + c) = pAl[q];
            *(uint2*)(Bh + r * GSA + c) = pBh[q];
            *(uint2*)(Bl + r * GSA + c) = pBl[q];
        }
    };

    int c0 = (ks * 512) / GK, c1 = ((ks + 1) * 512) / GK;
    LD(c0);
    for (int ch = c0; ch < c1; ++ch) {
        int buf = ch & 1;
        ST(buf);
        __syncthreads();
        if (ch + 1 < c1) LD(ch + 1);
        uint32_t sb = smem_u32(smg + buf * GBUF);
        uint32_t aH = sb, aL = sb + GTILE * 2, bH = sb + 4 * GTILE, bL = sb + 6 * GTILE;
#pragma unroll
        for (int k16 = 0; k16 < 32; k16 += 16) {
            uint32_t fah[2][4], fal[2][4], fbh[4][2], fbl[4][2];
            int arow = wm * 32 + (lane & 15), acol = k16 + ((lane >> 4) << 3);
#pragma unroll
            for (int ma = 0; ma < 2; ++ma) {
                uint32_t off = (uint32_t)((arow + ma * 16) * GSA + acol) * 2;
                ldm_x4(fah[ma], aH + off);
                ldm_x4(fal[ma], aL + off);
            }
            int brow = wn * 32 + (lane & 7), bcol = k16 + (lane & 8);
#pragma unroll
            for (int na = 0; na < 4; ++na) {
                uint32_t off = (uint32_t)((brow + na * 8) * GSA + bcol) * 2;
                ldm_x2(fbh[na], bH + off);
                ldm_x2(fbl[na], bL + off);
            }
#pragma unroll
            for (int ma = 0; ma < 2; ++ma)
#pragma unroll
                for (int na = 0; na < 4; ++na) {
                    MMA(acc[ma][na], fah[ma], fbh[na]);
                    MMA(acc[ma][na], fah[ma], fbl[na]);
                    MMA(acc[ma][na], fal[ma], fbh[na]);
                }
        }
        __syncthreads();
    }
    float* P = g_part + (((size_t)ks * NB + b) * 2 + mode) * (NC * NC);
#pragma unroll
    for (int ma = 0; ma < 2; ++ma)
#pragma unroll
        for (int na = 0; na < 4; ++na) {
            int r = i0 + wm * 32 + ma * 16 + (lane >> 2);
            int c = j0 + wn * 32 + na * 8 + (lane & 3) * 2;
            float2 v0 = make_float2(acc[ma][na][0], acc[ma][na][1]);
            float2 v1 = make_float2(acc[ma][na][2], acc[ma][na][3]);
            *(float2*)&P[(size_t)r * NC + c] = v0;
            *(float2*)&P[(size_t)(r + 8) * NC + c] = v1;
        }
}

__global__ __launch_bounds__(256) void k_gred() {
    int gid = blockIdx.x * 256 + threadIdx.x;
    if (gid >= NB * 2 * NC * NC) return;
    int e = gid % (NC * NC);
    int bm = gid / (NC * NC);
    int m = bm & 1, b = bm >> 1;
    int r = e / NC, c = e % NC;
    int esrc = (r >= 128 && c < 128) ? (c * NC + r) : e;
    float s = 0.f;
    for (int ks = 0; ks < GK; ++ks)
        s += g_part[(((size_t)ks * NB + b) * 2 + m) * (NC * NC) + esrc];
    (m == 0 ? g_C0 : g_Cf)[b * (NC * NC) + e] = s;
}

// ------------------------- 1x1 conv via mma.sync -----------------------------
#define CSA 40
#define CATILE (128 * CSA)
#define CBT 5120
#define CSB0 136
#define CBUFE (2 * CATILE + 2 * CBT)
#define CSMEM (2 * CBUFE * 2)
__global__ __launch_bounds__(256, 1) void k_conv_mma(int widx,
                                                     const float* __restrict__ bias,
                                                     float* __restrict__ Oout,
                                                     int mode) {
    extern __shared__ __align__(16) __nv_bfloat16 smc[];
    int tid = threadIdx.x, wid = tid >> 5, lane = tid & 31;
    int t0 = blockIdx.x * 128, o0 = blockIdx.y * 128, b = blockIdx.z;
    const unsigned short* Wh = g_wh + (size_t)widx * NC * NC;
    const unsigned short* Wl = g_wl + (size_t)widx * NC * NC;
    const unsigned short* Bxh = g_xh + (size_t)b * NC * NPIX;
    const unsigned short* Bxl = g_xl + (size_t)b * NC * NPIX;
    const uint32_t* Ybuf = g_y2 + (size_t)b * NPIX * NC;
    int wm = wid >> 2, wn = wid & 3;
    float acc[4][4][4] = {};
    uint2 pAh[4], pAl[4], pBh[4], pBl[4];
    uint32_t pY[16];

    auto LD = [&](int ch) {
        int k0 = ch * 32;
#pragma unroll
        for (int q = 0; q < 4; ++q) {
            int f = tid + q * 256, r = f >> 3, c = (f & 7) * 4;
            size_t off = (size_t)(o0 + r) * NC + k0 + c;
            pAh[q] = *(const uint2*)(Wh + off);
            pAl[q] = *(const uint2*)(Wl + off);
        }
        if (mode == 0) {
#pragma unroll
            for (int q = 0; q < 4; ++q) {
                int f = tid + q * 256, k = f >> 5, t = (f & 31) * 4;
                size_t off = (size_t)(k0 + k) * NPIX + t0 + t;
                pBh[q] = *(const uint2*)(Bxh + off);
                pBl[q] = *(const uint2*)(Bxl + off);
            }
        } else {
#pragma unroll
            for (int q = 0; q < 16; ++q) {
                int f = tid + q * 256, t = f >> 5, k = f & 31;
                pY[q] = Ybuf[(size_t)(t0 + t) * NC + k0 + k];
            }
        }
    };
    auto ST = [&](int buf) {
        __nv_bfloat16* Ah = smc + buf * CBUFE;
        __nv_bfloat16* Al = Ah + CATILE;
        unsigned short* Bh = (unsigned short*)(Ah + 2 * CATILE);
        unsigned short* Bl = Bh + CBT;
#pragma unroll
        for (int q = 0; q < 4; ++q) {
            int f = tid + q * 256, r = f >> 3, c = (f & 7) * 4;
            *(uint2*)(Ah + r * CSA + c) = pAh[q];
            *(uint2*)(Al + r * CSA + c) = pAl[q];
        }
        if (mode == 0) {
#pragma unroll
            for (int q = 0; q < 4; ++q) {
                int f = tid + q * 256, k = f >> 5, t = (f & 31) * 4;
                *(uint2*)(Bh + k * CSB0 + t) = pBh[q];
                *(uint2*)(Bl + k * CSB0 + t) = pBl[q];
            }
        } else {
#pragma unroll
            for (int q = 0; q < 16; ++q) {
                int f = tid + q * 256, t = f >> 5, k = f & 31;
                uint32_t v = pY[q];
                Bh[t * 40 + k] = (unsigned short)(v & 0xFFFF);
                Bl[t * 40 + k] = (unsigned short)(v >> 16);
            }
        }
    };

    LD(0);
    for (int ch = 0; ch < 8; ++ch) {
        int buf = ch & 1;
        ST(buf);
        __syncthreads();
        if (ch < 7) LD(ch + 1);
        uint32_t sb = smem_u32(smc + buf * CBUFE);
        uint32_t aH = sb, aL = sb + CATILE * 2, bH = sb + 4 * CATILE, bL = bH + CBT * 2;
#pragma unroll
        for (int k16 = 0; k16 < 32; k16 += 16) {
            uint32_t fah[4][4], fal[4][4], fbh[4][2], fbl[4][2];
            int arow = wm * 64 + (lane & 15), acol = k16 + ((lane >> 4) << 3);
#pragma unroll
            for (int ma = 0; ma < 4; ++ma) {
                uint32_t off = (uint32_t)((arow + ma * 16) * CSA + acol) * 2;
                ldm_x4(fah[ma], aH + off);
                ldm_x4(fal[ma], aL + off);
            }
            if (mode == 0) {
                int krow = k16 + (lane & 15);
#pragma unroll
                for (int na = 0; na < 4; ++na) {
                    uint32_t off = (uint32_t)(krow * CSB0 + wn * 32 + na * 8) * 2;
                    ldm_x2t(fbh[na], bH + off);
                    ldm_x2t(fbl[na], bL + off);
                }
            } else {
                int brow = wn * 32 + (lane & 7), bcol = k16 + (lane & 8);
#pragma unroll
                for (int na = 0; na < 4; ++na) {
                    uint32_t off = (uint32_t)((brow + na * 8) * 40 + bcol) * 2;
                    ldm_x2(fbh[na], bH + off);
                    ldm_x2(fbl[na], bL + off);
                }
            }
#pragma unroll
            for (int ma = 0; ma < 4; ++ma)
#pragma unroll
                for (int na = 0; na < 4; ++na) {
                    MMA(acc[ma][na], fah[ma], fbh[na]);
                    MMA(acc[ma][na], fah[ma], fbl[na]);
                    MMA(acc[ma][na], fal[ma], fbh[na]);
                }
        }
        __syncthreads();
    }
#pragma unroll
    for (int ma = 0; ma < 4; ++ma) {
        int r = o0 + wm * 64 + ma * 16 + (lane >> 2);
        float b0v = bias[r], b1v = bias[r + 8];
#pragma unroll
        for (int na = 0; na < 4; ++na) {
            int c = t0 + wn * 32 + na * 8 + (lane & 3) * 2;
            if (mode == 0) {
                uint32_t h0, l0, h1, l1;
                pack2(acc[ma][na][0] + b0v, acc[ma][na][1] + b0v, h0, l0);
                pack2(acc[ma][na][2] + b1v, acc[ma][na][3] + b1v, h1, l1);
                size_t i0v = (size_t)(b * NC + r) * NPIX + c;
                *(uint32_t*)(g_vsh + i0v) = h0;
                *(uint32_t*)(g_vsl + i0v) = l0;
                size_t i1v = i0v + (size_t)8 * NPIX;
                *(uint32_t*)(g_vsh + i1v) = h1;
                *(uint32_t*)(g_vsl + i1v) = l1;
            } else {
                float* O = Oout + (size_t)b * NC * NPIX;
                float2 v0 = make_float2(acc[ma][na][0] + b0v, acc[ma][na][1] + b0v);
                float2 v1 = make_float2(acc[ma][na][2] + b1v, acc[ma][na][3] + b1v);
                *(float2*)&O[(size_t)r * NPIX + c] = v0;
                *(float2*)&O[(size_t)(r + 8) * NPIX + c] = v1;
            }
        }
    }
}

// ------------------------- P matrices: A @ W^T (FFMA) ------------------------
__global__ __launch_bounds__(256) void k_mm256(const float* __restrict__ w1,
                                               const float* __restrict__ w2) {
    int tile = blockIdx.x, b = blockIdx.y, z = blockIdx.z;
    const float* A = (z == 0 ? g_Cf : g_C0) + (size_t)b * NC * NC;
    const float* W = (z == 1 ? w1 : w2);
    float* P = g_P + ((size_t)z * NB + b) * NC * NC;
    int i0 = (tile >> 2) * 64, j0 = (tile & 3) * 64;
    __shared__ float As[64][33], Bs[64][33];
    float acc[4][4] = {};
    int ty = threadIdx.x >> 4, tx = threadIdx.x & 15;
    for (int kb = 0; kb < NC; kb += 32) {
        for (int idx = threadIdx.x; idx < 64 * 32; idx += 256) {
            int r = idx >> 5, c = idx & 31;
            As[r][c] = A[(i0 + r) * NC + kb + c];
            Bs[r][c] = W[(j0 + r) * NC + kb + c];
        }
        __syncthreads();
#pragma unroll
        for (int kk = 0; kk < 32; ++kk) {
            float a[4], bv[4];
#pragma unroll
            for (int ii = 0; ii < 4; ++ii) a[ii] = As[ty + 16 * ii][kk];
#pragma unroll
            for (int jj = 0; jj < 4; ++jj) bv[jj] = Bs[tx + 16 * jj][kk];
#pragma unroll
            for (int ii = 0; ii < 4; ++ii)
#pragma unroll
                for (int jj = 0; jj < 4; ++jj) acc[ii][jj] += a[ii] * bv[jj];
        }
        __syncthreads();
    }
    for (int ii = 0; ii < 4; ++ii)
        for (int jj = 0; jj < 4; ++jj)
            P[(i0 + ty + 16 * ii) * NC + j0 + tx + 16 * jj] = acc[ii][jj];
}

// ------------------------- attn -> softmax -> ifft_c -------------------------
__global__ __launch_bounds__(256) void k_attn(const float* __restrict__ w1,
                                              const float* __restrict__ w2,
                                              const float* __restrict__ b1,
                                              const float* __restrict__ b2,
                                              const float* __restrict__ temp) {
    int b = blockIdx.x >> 3, h = blockIdx.x & 7;
    int tid = threadIdx.x;
    __shared__ float Ps[NC][33];
    __shared__ float numS[CH][33];
    __shared__ float redA[CH][8], redB[CH][8];
    __shared__ float qn[CH], kn[CH], w1s[CH], w2s[CH];
    const float* P1 = g_P + ((size_t)0 * NB + b) * NC * NC;
    const float* P2 = g_P + ((size_t)1 * NB + b) * NC * NC;
    const float* P3 = g_P + ((size_t)2 * NB + b) * NC * NC;
    const float* Sb = g_S + b * NC;

    for (int idx = tid; idx < NC * CH; idx += 256)
        Ps[idx >> 5][idx & 31] = P1[(size_t)(idx >> 5) * NC + h * CH + (idx & 31)];
    __syncthreads();
    {
        int c = tid >> 3, dg = tid & 7;
        float acc[4] = {0.f, 0.f, 0.f, 0.f};
        const float* wrow = w1 + (size_t)(h * CH + c) * NC;
        for (int j = 0; j < NC; ++j) {
            float w = wrow[j];
#pragma unroll
            for (int q = 0; q < 4; ++q) acc[q] += w * Ps[j][dg + 8 * q];
        }
#pragma unroll
        for (int q = 0; q < 4; ++q) numS[c][dg + 8 * q] = acc[q];
    }
    __syncthreads();

    for (int idx = tid; idx < NC * CH; idx += 256)
        Ps[idx >> 5][idx & 31] = P2[(size_t)(idx >> 5) * NC + h * CH + (idx & 31)];
    __syncthreads();
    {
        int c = tid >> 3, g = tid & 7;
        const float* wrow = w1 + (size_t)(h * CH + c) * NC;
        float pa = 0.f, pb = 0.f;
        for (int j = g * 32; j < g * 32 + 32; ++j) {
            float w = wrow[j];
            pa += w * Ps[j][c];
            pb += w * Sb[j];
        }
        redA[c][g] = pa; redB[c][g] = pb;
    }
    __syncthreads();
    if (tid < CH) {
        float a = 0.f, bb = 0.f;
        for (int g = 0; g < 8; ++g) { a += redA[tid][g]; bb += redB[tid][g]; }
        float b1c = b1[h * CH + tid];
        w1s[tid] = bb;
        qn[tid] = fmaxf(sqrtf(fmaxf(a + 2.f * b1c * bb + 16384.f * b1c * b1c, 0.f)), 1e-12f);
    }
    __syncthreads();

    for (int idx = tid; idx < NC * CH; idx += 256)
        Ps[idx >> 5][idx & 31] = P3[(size_t)(idx >> 5) * NC + h * CH + (idx & 31)];
    __syncthreads();
    {
        int c = tid >> 3, g = tid & 7;
        const float* wrow = w2 + (size_t)(h * CH + c) * NC;
        float pa = 0.f, pb = 0.f;
        for (int j = g * 32; j < g * 32 + 32; ++j) {
            float w = wrow[j];
            pa += w * Ps[j][c];
            pb += w * Sb[j];
        }
        redA[c][g] = pa; redB[c][g] = pb;
    }
    __syncthreads();
    if (tid < CH) {
        float a = 0.f, bb = 0.f;
        for (int g = 0; g < 8; ++g) { a += redA[tid][g]; bb += redB[tid][g]; }
        float b2d = b2[h * CH + tid];
        w2s[tid] = bb;
        kn[tid] = fmaxf(sqrtf(fmaxf(a + 2.f * b2d * bb + 16384.f * b2d * b2d, 0.f)), 1e-12f);
    }
    __syncthreads();

    {
        float tH = temp[h];
        for (int idx = tid; idx < CH * CH; idx += 256) {
            int c = idx >> 5, d = idx & 31;
            float b1c = b1[h * CH + c], b2d = b2[h * CH + d];
            float numF = numS[c][d] + b1c * w2s[d] + b2d * w1s[c] + 16384.f * b1c * b2d;
            numS[c][d] = tH * numF / (qn[c] * kn[d]);
        }
    }
    __syncthreads();

    if (tid < CH) {
        float mx = -1e30f;
        for (int d = 0; d < CH; ++d) mx = fmaxf(mx, numS[tid][d]);
        float s = 0.f;
        for (int d = 0; d < CH; ++d) { float e = expf(numS[tid][d] - mx); numS[tid][d] = e; s += e; }
        float inv = 1.f / s;
        for (int d = 0; d < CH; ++d) numS[tid][d] *= inv;
    }
    __syncthreads();

    for (int idx = tid; idx < CH * CH; idx += 256) {
        int cp = idx >> 5, d = idx & 31;
        float re = 0.f, im = 0.f;
        for (int c = 0; c < CH; ++c) {
            int ph = (c * cp) & 31;
            float sv, cv;
            sincosf(0.19634954084936207f * (float)ph, &sv, &cv);
            float a = numS[c][d];
            re += a * cv; im += a * sv;
        }
        re *= 0.03125f; im *= 0.03125f;
        if (cp == 0) im += 0.03125f;
        g_At[((size_t)blockIdx.x * CH + cp) * CH + d] = make_float2(re, im);
    }
}

// ------------------------- Dirichlet table + bf16 expansion ------------------
__global__ __launch_bounds__(256) void k_dtab() {
    int i = blockIdx.x * 256 + threadIdx.x;
    if (i >= 128 * 255) return;
    int s = i / 255, mi = i % 255, m = mi - 127;
    float2 v;
    if (s == 0) {
        v = make_float2(m == 0 ? 1.f : 0.f, 0.f);
    } else {
        double f = (double)s / 128.0;
        double al = (double)m + f;
        double mag = sinpi(f) / (128.0 * sinpi(al / 128.0));
        if (m & 1) mag = -mag;
        double ph = al * (127.0 / 128.0);
        v = make_float2((float)(cospi(ph) * mag), (float)(sinpi(ph) * mag));
    }
    g_Dtab[s * 256 + mi] = v;
}
__global__ __launch_bounds__(256) void k_dexp() {
    int gid = blockIdx.x * 256 + threadIdx.x;
    int x = gid & 127, p = (gid >> 7) & 127, s = gid >> 14;
    float2 v = g_Dtab[s * 256 + (p - x + 127)];
    __nv_bfloat16 hr = __float2bfloat16_rn(v.x);
    __nv_bfloat16 hi = __float2bfloat16_rn(v.y);
    g_DreH[gid] = __bfloat16_as_ushort(hr);
    g_DreL[gid] = __bfloat16_as_ushort(__float2bfloat16_rn(v.x - __bfloat162float(hr)));
    g_DimH[gid] = __bfloat16_as_ushort(hi);
    g_DimL[gid] = __bfloat16_as_ushort(__float2bfloat16_rn(v.y - __bfloat162float(hi)));
}

// ------------------------- fused Dirichlet transform + channel attn ----------
#define FSA 40
#define FGEMM 51200
#define FEPI (66560 + 2 * 2112 * 4)
#define FSMEM (FEPI > FGEMM ? FEPI : FGEMM)
__global__ __launch_bounds__(256, 1) void k_fft_fused() {
    extern __shared__ __align__(16) char smf[];
    __nv_bfloat16* smb = (__nv_bfloat16*)smf;
    int tid = threadIdx.x, wid = tid >> 5, lane = tid & 31;
    int s = blockIdx.x;
    int b = blockIdx.y >> 2, dblk = blockIdx.y & 3;
    int d0 = dblk * 64;
    int wm = wid >> 1, wn = wid & 1;
    float accRe[2][4][4] = {}, accIm[2][4][4] = {};
    const uint32_t sb = smem_u32(smf);
    const uint32_t oReH = 0, oReL = 5120, oImH = 10240, oImL = 15360, oBH = 20480, oBL = 23040;

    for (int kc = 0; kc < 128; kc += 32) {
        __syncthreads();
#pragma unroll
        for (int q = 0; q < 4; ++q) {
            int f = tid + q * 256, r = f >> 3, c = (f & 7) * 4;
            size_t so = (size_t)s * 16384 + r * 128 + kc + c;
            uint32_t dofs = r * FSA + c;
            *(uint2*)(smb + oReH + dofs) = *(const uint2*)(g_DreH + so);
            *(uint2*)(smb + oReL + dofs) = *(const uint2*)(g_DreL + so);
            *(uint2*)(smb + oImH + dofs) = *(const uint2*)(g_DimH + so);
            *(uint2*)(smb + oImL + dofs) = *(const uint2*)(g_DimL + so);
        }
#pragma unroll
        for (int q = 0; q < 2; ++q) {
            int f = tid + q * 256, r = f >> 3, c = (f & 7) * 4;
            size_t so = (size_t)(b * NC + d0 + r) * NPIX + s * 128 + kc + c;
            uint32_t dofs = r * FSA + c;
            *(uint2*)(smb + oBH + dofs) = *(const uint2*)(g_vsh + so);
            *(uint2*)(smb + oBL + dofs) = *(const uint2*)(g_vsl + so);
        }
        __syncthreads();
#pragma unroll
        for (int k16 = 0; k16 < 32; k16 += 16) {
            uint32_t fbh[4][2], fbl[4][2];
            int brow = wn * 32 + (lane & 7), bcol = k16 + (lane & 8);
#pragma unroll
            for (int na = 0; na < 4; ++na) {
                uint32_t off = (uint32_t)((brow + na * 8) * FSA + bcol) * 2;
                ldm_x2(fbh[na], sb + oBH * 2 + off);
                ldm_x2(fbl[na], sb + oBL * 2 + off);
            }
            int arow = wm * 32 + (lane & 15), acol = k16 + ((lane >> 4) << 3);
            {
                uint32_t fh[2][4], fl[2][4];
#pragma unroll
                for (int ma = 0; ma < 2; ++ma) {
                    uint32_t off = (uint32_t)((arow + ma * 16) * FSA + acol) * 2;
                    ldm_x4(fh[ma], sb + oReH * 2 + off);
                    ldm_x4(fl[ma], sb + oReL * 2 + off);
                }
#pragma unroll
                for (int ma = 0; ma < 2; ++ma)
#pragma unroll
                    for (int na = 0; na < 4; ++na) {
                        MMA(accRe[ma][na], fh[ma], fbh[na]);
                        MMA(accRe[ma][na], fh[ma], fbl[na]);
                        MMA(accRe[ma][na], fl[ma], fbh[na]);
                    }
            }
            {
                uint32_t fh[2][4], fl[2][4];
#pragma unroll
                for (int ma = 0; ma < 2; ++ma) {
                    uint32_t off = (uint32_t)((arow + ma * 16) * FSA + acol) * 2;
                    ldm_x4(fh[ma], sb + oImH * 2 + off);
                    ldm_x4(fl[ma], sb + oImL * 2 + off);
                }
#pragma unroll
                for (int ma = 0; ma < 2; ++ma)
#pragma unroll
                    for (int na = 0; na < 4; ++na) {
                        MMA(accIm[ma][na], fh[ma], fbh[na]);
                        MMA(accIm[ma][na], fh[ma], fbl[na]);
                        MMA(accIm[ma][na], fl[ma], fbh[na]);
                    }
            }
        }
    }
    __syncthreads();
    float2* VtS = (float2*)smf;
    float* Are = (float*)(smf + 66560);
    float* Aim = Are + 2112;
#pragma unroll
    for (int ma = 0; ma < 2; ++ma)
#pragma unroll
        for (int na = 0; na < 4; ++na) {
            int p = wm * 32 + ma * 16 + (lane >> 2);
            int d = wn * 32 + na * 8 + (lane & 3) * 2;
            VtS[p * 65 + d]     = make_float2(accRe[ma][na][0], accIm[ma][na][0]);
            VtS[p * 65 + d + 1] = make_float2(accRe[ma][na][1], accIm[ma][na][1]);
            VtS[(p + 8) * 65 + d]     = make_float2(accRe[ma][na][2], accIm[ma][na][2]);
            VtS[(p + 8) * 65 + d + 1] = make_float2(accRe[ma][na][3], accIm[ma][na][3]);
        }
    int h0 = dblk * 2;
    for (int idx = tid; idx < 2048; idx += 256) {
        int hh = idx >> 10, rest = idx & 1023, c = rest >> 5, d = rest & 31;
        float2 a = g_At[(size_t)(b * NHEADS + h0 + hh) * 1024 + c * 32 + d];
        Are[(hh * 32 + c) * 33 + d] = a.x;
        Aim[(hh * 32 + c) * 33 + d] = a.y;
    }
    __syncthreads();
    int pg = tid >> 5, cg = tid & 31;
    int head = cg >> 4, cl0 = (2 * cg) & 31;
    const float* ArH = Are + head * 1056;
    const float* AiH = Aim + head * 1056;
    float accr[2][16] = {}, acci[2][16] = {};
    for (int d = 0; d < 32; ++d) {
        float a0r = ArH[cl0 * 33 + d],       a0i = AiH[cl0 * 33 + d];
        float a1r = ArH[(cl0 + 1) * 33 + d], a1i = AiH[(cl0 + 1) * 33 + d];
        int dv = head * 32 + d;
#pragma unroll
        for (int i = 0; i < 16; ++i) {
            float2 v = VtS[(pg * 16 + i) * 65 + dv];
            accr[0][i] += a0r * v.x - a0i * v.y;
            acci[0][i] += a0r * v.y + a0i * v.x;
            accr[1][i] += a1r * v.x - a1i * v.y;
            acci[1][i] += a1r * v.y + a1i * v.x;
        }
    }
    uint32_t* Y = g_y2 + (size_t)b * NPIX * NC;
#pragma unroll
    for (int i = 0; i < 16; ++i) {
        int p = pg * 16 + i;
        int t = (p << 7) + s;
        float y0 = sqrtf(accr[0][i] * accr[0][i] + acci[0][i] * acci[0][i]);
        float y1 = sqrtf(accr[1][i] * accr[1][i] + acci[1][i] * acci[1][i]);
        uint2 w;
        w.x = pack_hl(y0);
        w.y = pack_hl(y1);
        *(uint2*)&Y[(size_t)t * NC + d0 + 2 * cg] = w;
    }
}

// ------------------------- launch --------------------------------------------
extern "C" void kernel_launch(void* const* d_in, const int* in_sizes, int n_in,
                              void* d_out, int out_size) {
    const float* x  = (const float*)d_in[0];
    const float* w1 = (const float*)d_in[1];
    const float* b1 = (const float*)d_in[2];
    const float* w2 = (const float*)d_in[3];
    const float* b2 = (const float*)d_in[4];
    const float* w3 = (const float*)d_in[5];
    const float* b3 = (const float*)d_in[6];
    const float* wo = (const float*)d_in[7];
    const float* bo = (const float*)d_in[8];
    const float* temp = (const float*)d_in[9];
    float* out = (float*)d_out;

    static cudaStream_t s1 = nullptr, s2 = nullptr;
    static cudaEvent_t evR = nullptr, evS = nullptr, evG = nullptr, evD = nullptr;
    if (s1 == nullptr) {
        cudaStreamCreateWithFlags(&s1, cudaStreamNonBlocking);
        cudaStreamCreateWithFlags(&s2, cudaStreamNonBlocking);
        cudaEventCreateWithFlags(&evR, cudaEventDisableTiming);
        cudaEventCreateWithFlags(&evS, cudaEventDisableTiming);
        cudaEventCreateWithFlags(&evG, cudaEventDisableTiming);
        cudaEventCreateWithFlags(&evD, cudaEventDisableTiming);
        cudaFuncSetAttribute(k_gram_mma, cudaFuncAttributeMaxDynamicSharedMemorySize, GSMEM);
        cudaFuncSetAttribute(k_conv_mma, cudaFuncAttributeMaxDynamicSharedMemorySize, CSMEM);
        cudaFuncSetAttribute(k_fft_fused, cudaFuncAttributeMaxDynamicSharedMemorySize, FSMEM);
    }

    // branch s2: Dirichlet tables (independent until k_fft_fused)
    cudaEventRecord(evR, 0);
    cudaStreamWaitEvent(s2, evR, 0);
    k_dtab<<<128, 256, 0, s2>>>();
    k_dexp<<<8192, 256, 0, s2>>>();
    cudaEventRecord(evD, s2);

    // main: x split (+flip +sums) — the sole serial prefix
    k_sumsplit<<<NB * NC, 256>>>(x);
    cudaEventRecord(evS, 0);

    // branch s1: gram chain (concurrent with wsplit+conv0 on main)
    cudaStreamWaitEvent(s1, evS, 0);
    k_gram_mma<<<dim3(3, NB, GK * 2), 512, GSMEM, s1>>>();
    k_gred<<<(NB * 2 * NC * NC) / 256, 256, 0, s1>>>();
    k_mm256<<<dim3(16, NB, 3), 256, 0, s1>>>(w1, w2);
    k_attn<<<NB * NHEADS, 256, 0, s1>>>(w1, w2, b1, b2, temp);
    cudaEventRecord(evG, s1);

    // main: weight split then conv0
    k_wsplit<<<2 * NC * NC / 4 / 256, 256>>>(w3, wo);
    k_conv_mma<<<dim3(128, 2, NB), 256, CSMEM>>>(0, b3, nullptr, 0);

    // join: fft needs conv0 (main), attn (s1), dexp (s2)
    cudaStreamWaitEvent(0, evG, 0);
    cudaStreamWaitEvent(0, evD, 0);
    k_fft_fused<<<dim3(128, 16), 256, FSMEM>>>();
    k_conv_mma<<<dim3(128, 2, NB), 256, CSMEM>>>(1, bo, out, 1);
}